// round 10
// baseline (speedup 1.0000x reference)
#include <cuda_runtime.h>
#include <cstdint>

#define NN 50000
#define EE 1000000
#define RR 8
#define BB 30
#define DIN 64
#define H1 64
#define H2 64

// ---------------- scratch (static device globals; no runtime allocation) ---
__device__ __align__(16) float g_Wrel[RR * DIN * H1];       // 128 KB
__device__ __align__(16) float g_xr[(size_t)NN * RR * H1];  // 102.4 MB xr[n][r][o]
__device__ __align__(16) float g_h[NN * H1];                // 12.8 MB
__device__ int      g_deg_out[NN];
__device__ int      g_cnt[NN];
__device__ int      g_off[NN + 1];
__device__ int      g_cursor[NN];
__device__ unsigned g_csr[EE];                              // src*8 + etype, CSR by dst
__device__ int      g_ei64;                                 // edge_index is int64?
__device__ int      g_et64;                                 // edge_type  is int64?

// Read index element i from a buffer that is either int32[] or int64[] (LE).
__device__ __forceinline__ int ld_ei(const int* __restrict__ p, long long i) {
    return g_ei64 ? p[2 * i] : p[(int)i];
}
__device__ __forceinline__ int ld_et(const int* __restrict__ p, long long i) {
    return g_et64 ? p[2 * i] : p[(int)i];
}

// ---------------- K-1: detect whether index buffers are int64 or int32 ----
// For int64 little-endian values in [0, 2^31), every odd 32-bit word is 0.
// For genuine int32 index data (values ~U[0,N) or U[0,R)), that probability
// is ~0 across 64 consecutive entries.
__global__ void k_detect(const int* __restrict__ ei,
                         const int* __restrict__ et) {
    if (threadIdx.x == 0 && blockIdx.x == 0) {
        int a = 1, b = 1;
        for (int e = 0; e < 64; e++) {
            if (ei[2 * e + 1] != 0) a = 0;
            if (et[2 * e + 1] != 0) b = 0;
        }
        // edge_type values are in [0,8): low word nonzero only ~7/8 of the
        // time, but across 64 entries the all-hi-zero test is still decisive.
        g_ei64 = a;
        g_et64 = b;
    }
}

// ---------------- K0: Wrel = comp @ basis, plus zeroing of count arrays ----
__global__ void k_init(const float* __restrict__ basis,
                       const float* __restrict__ comp) {
    int idx = blockIdx.x * blockDim.x + threadIdx.x;
    if (idx < NN) { g_deg_out[idx] = 0; g_cnt[idx] = 0; }
    if (idx < RR * DIN * H1) {
        int r  = idx / (DIN * H1);
        int io = idx % (DIN * H1);
        float s = 0.f;
#pragma unroll
        for (int b = 0; b < BB; b++)
            s += comp[r * BB + b] * basis[b * DIN * H1 + io];
        g_Wrel[idx] = s;
    }
}

// ---------------- CSR build ------------------------------------------------
__global__ void k_count(const int* __restrict__ ei) {
    int e = blockIdx.x * blockDim.x + threadIdx.x;
    if (e < EE) {
        int s = ld_ei(ei, e);
        int d = ld_ei(ei, (long long)EE + e);
        atomicAdd(&g_deg_out[s], 1);                 // src histogram
        atomicAdd(&g_cnt[d], 1);                     // dst histogram
    }
}

// single-block exclusive scan of g_cnt -> g_off (+ cursor init)
__global__ void k_scan() {
    const int CH = (NN + 1023) / 1024;   // 49
    __shared__ int sh[1024];
    int t = threadIdx.x;
    int start = t * CH;
    int sum = 0;
    for (int j = 0; j < CH; j++) {
        int i = start + j;
        if (i < NN) sum += g_cnt[i];
    }
    sh[t] = sum;
    __syncthreads();
    for (int d = 1; d < 1024; d <<= 1) {
        int v = (t >= d) ? sh[t - d] : 0;
        __syncthreads();
        sh[t] += v;
        __syncthreads();
    }
    int run = sh[t] - sum;               // exclusive base
    for (int j = 0; j < CH; j++) {
        int i = start + j;
        if (i < NN) {
            g_off[i] = run;
            g_cursor[i] = run;
            run += g_cnt[i];
        }
    }
    if (t == 1023) g_off[NN] = sh[1023];
}

__global__ void k_scatter(const int* __restrict__ ei,
                          const int* __restrict__ et) {
    int e = blockIdx.x * blockDim.x + threadIdx.x;
    if (e < EE) {
        int s = ld_ei(ei, e);
        int d = ld_ei(ei, (long long)EE + e);
        int r = ld_et(et, e);
        int pos = atomicAdd(&g_cursor[d], 1);
        g_csr[pos] = (unsigned)(s * RR + r);
    }
}

// ---------------- K1: xr[n,r,:] = x @ Wrel_r ; h_init = x @ loopW + b1 -----
// 64-node tile, 9 weight matrices. A stored transposed with +1 pad (scalar
// LDS, conflict-free); W read as float4 rows (LDS.128, conflict-free).
// Each thread: 4 nodes x 4 output cols -> 16 FFMA + 5 LDS per k.
__global__ __launch_bounds__(256) void k_xr(const float* __restrict__ x,
                                            const float* __restrict__ loopw,
                                            const float* __restrict__ bias1) {
    __shared__ __align__(16) float At[64][65];       // A transposed, padded
    __shared__ __align__(16) float Ws[64][64];       // current W
    int t  = threadIdx.x;
    int n0 = blockIdx.x * 64;

    // load x tile (coalesced), store transposed (pad kills store conflicts)
    for (int it = 0; it < 16; it++) {
        int idx = t + it * 256;
        int nl = idx >> 6, k = idx & 63;
        int n = n0 + nl;
        At[k][nl] = (n < NN) ? x[n * DIN + k] : 0.f;
    }

    int tx = t & 15, ty = t >> 4;                    // cols tx*4.., nodes ty*4..
    float b1r[4];
#pragma unroll
    for (int q = 0; q < 4; q++) b1r[q] = bias1[tx * 4 + q];

    for (int m = 0; m < 9; m++) {
        const float* W = (m < 8) ? (g_Wrel + m * DIN * H1) : loopw;
        __syncthreads();
        for (int it = 0; it < 16; it++) {
            int idx = t + it * 256;
            ((float*)Ws)[idx] = W[idx];
        }
        __syncthreads();

        float c[4][4];
#pragma unroll
        for (int j = 0; j < 4; j++)
#pragma unroll
            for (int q = 0; q < 4; q++) c[j][q] = 0.f;

#pragma unroll 8
        for (int k = 0; k < 64; k++) {
            float4 b = *(const float4*)&Ws[k][tx * 4];
            float a0 = At[k][ty * 4 + 0];
            float a1 = At[k][ty * 4 + 1];
            float a2 = At[k][ty * 4 + 2];
            float a3 = At[k][ty * 4 + 3];
            c[0][0] += a0 * b.x; c[0][1] += a0 * b.y; c[0][2] += a0 * b.z; c[0][3] += a0 * b.w;
            c[1][0] += a1 * b.x; c[1][1] += a1 * b.y; c[1][2] += a1 * b.z; c[1][3] += a1 * b.w;
            c[2][0] += a2 * b.x; c[2][1] += a2 * b.y; c[2][2] += a2 * b.z; c[2][3] += a2 * b.w;
            c[3][0] += a3 * b.x; c[3][1] += a3 * b.y; c[3][2] += a3 * b.z; c[3][3] += a3 * b.w;
        }

#pragma unroll
        for (int j = 0; j < 4; j++) {
            int n = n0 + ty * 4 + j;
            if (n < NN) {
                float4 o = make_float4(c[j][0], c[j][1], c[j][2], c[j][3]);
                if (m < 8) {
                    *(float4*)&g_xr[((size_t)n * 8 + m) * 64 + tx * 4] = o;
                } else {
                    o.x += b1r[0]; o.y += b1r[1]; o.z += b1r[2]; o.w += b1r[3];
                    *(float4*)&g_h[n * 64 + tx * 4] = o;
                }
            }
        }
    }
}

// ---------------- K2: h[d] += sum over in-edges of xr[src*8+et] -----------
// warp per dst; csr indices fetched coalesced then shfl'd; each lane owns
// dims {2l, 2l+1} -> the warp reads the full 256B row contiguously.
// Inner loop unrolled x4 so the gather LDGs batch (MLP >= 4).
__global__ __launch_bounds__(256) void k_agg1() {
    int w = (blockIdx.x * 256 + threadIdx.x) >> 5;   // dst node
    int l = threadIdx.x & 31;
    int beg = g_off[w], end = g_off[w + 1];
    float ax = 0.f, ay = 0.f;
    for (int cb = beg; cb < end; cb += 32) {
        int mcnt = min(32, end - cb);
        unsigned myrow = (l < mcnt) ? g_csr[cb + l] : 0u;
#pragma unroll 4
        for (int j = 0; j < mcnt; j++) {
            unsigned row = __shfl_sync(0xffffffffu, myrow, j);
            float2 v = *(const float2*)&g_xr[(size_t)row * 64 + 2 * l];
            ax += v.x; ay += v.y;
        }
    }
    float2 h = *(float2*)&g_h[w * 64 + 2 * l];
    h.x += ax; h.y += ay;
    *(float2*)&g_h[w * 64 + 2 * l] = h;
}

// ---------------- K3: GraphConv gather + fused 64x64 GEMM + bias ----------
// warp per dst: agg2 = sum_e h[src]*rsqrt(deg_out[src]), scaled by
// rsqrt(deg_in); out = agg2 @ W2 + b2 via smem-staged vector.
__global__ __launch_bounds__(256) void k_out(const float* __restrict__ w2,
                                             const float* __restrict__ bias2,
                                             float* __restrict__ out) {
    __shared__ __align__(16) float Ws[64][64];       // 16 KB
    __shared__ float vbuf[8][64];                    // 2 KB
    int t = threadIdx.x;
    for (int it = 0; it < 16; it++)
        ((float*)Ws)[t + it * 256] = w2[t + it * 256];
    __syncthreads();

    int w  = (blockIdx.x * 256 + t) >> 5;            // dst node
    int wl = t >> 5;
    int l  = t & 31;
    int beg = g_off[w], end = g_off[w + 1];

    float ax = 0.f, ay = 0.f;
    for (int cb = beg; cb < end; cb += 32) {
        int mcnt = min(32, end - cb);
        unsigned myrow = (l < mcnt) ? g_csr[cb + l] : 0u;
#pragma unroll 4
        for (int j = 0; j < mcnt; j++) {
            unsigned row = __shfl_sync(0xffffffffu, myrow, j);
            int src = (int)(row >> 3);
            float sc = rsqrtf((float)max(g_deg_out[src], 1));
            float2 v = *(const float2*)&g_h[src * 64 + 2 * l];
            ax += v.x * sc; ay += v.y * sc;
        }
    }
    float si = rsqrtf((float)max(end - beg, 1));
    ax *= si; ay *= si;

    vbuf[wl][2 * l]     = ax;
    vbuf[wl][2 * l + 1] = ay;
    __syncwarp();

    float ox = 0.f, oy = 0.f;
#pragma unroll 16
    for (int i = 0; i < 64; i++) {
        float v = vbuf[wl][i];                       // broadcast
        float2 wv = *(const float2*)&Ws[i][2 * l];   // conflict-free
        ox += v * wv.x; oy += v * wv.y;
    }
    ox += bias2[2 * l];
    oy += bias2[2 * l + 1];
    out[w * 64 + 2 * l]     = ox;
    out[w * 64 + 2 * l + 1] = oy;
}

// ---------------- launch ---------------------------------------------------
extern "C" void kernel_launch(void* const* d_in, const int* in_sizes, int n_in,
                              void* d_out, int out_size) {
    const float* x     = (const float*)d_in[0];
    const int*   ei    = (const int*)d_in[1];     // edge_index (int32 or int64)
    // d_in[2] = edge_norm (unused by the reference computation)
    const int*   et    = (const int*)d_in[3];     // edge_type  (int32 or int64)
    const float* basis = (const float*)d_in[4];
    const float* comp  = (const float*)d_in[5];
    const float* loopw = (const float*)d_in[6];
    const float* b1    = (const float*)d_in[7];
    const float* w2    = (const float*)d_in[8];
    const float* b2    = (const float*)d_in[9];
    float* out = (float*)d_out;

    k_detect <<<1, 32>>>(ei, et);
    k_init   <<<(NN + 255) / 256, 256>>>(basis, comp);
    k_count  <<<(EE + 255) / 256, 256>>>(ei);
    k_scan   <<<1, 1024>>>();
    k_scatter<<<(EE + 255) / 256, 256>>>(ei, et);
    k_xr     <<<(NN + 63) / 64, 256>>>(x, loopw, b1);
    k_agg1   <<<NN / 8, 256>>>();
    k_out    <<<NN / 8, 256>>>(w2, b2, out);
}

// round 12
// speedup vs baseline: 1.2922x; 1.2922x over previous
#include <cuda_runtime.h>
#include <cstdint>

#define NN 50000
#define EE 1000000
#define RR 8
#define BB 30
#define DIN 64
#define H1 64
#define H2 64
#define SCAN_NB ((NN + 1023) / 1024)   // 49

// ---------------- scratch (static device globals; no runtime allocation) ---
__device__ __align__(16) float g_Wrel[RR * DIN * H1];       // 128 KB
__device__ __align__(16) float g_xr[(size_t)NN * RR * H1];  // 102.4 MB xr[n][r][o]
__device__ __align__(16) float g_h[NN * H1];                // 12.8 MB
__device__ int      g_deg_out[NN];
__device__ int      g_cnt[NN];
__device__ int      g_off[NN + 1];
__device__ int      g_cursor[NN];
__device__ int      g_bsum[SCAN_NB];
__device__ unsigned g_csr[EE];                              // src*8 + etype, CSR by dst
__device__ int      g_ei64;                                 // edge_index is int64?
__device__ int      g_et64;                                 // edge_type  is int64?

// Read index element i from a buffer that is either int32[] or int64[] (LE).
__device__ __forceinline__ int ld_ei(const int* __restrict__ p, long long i) {
    return g_ei64 ? p[2 * i] : p[(int)i];
}
__device__ __forceinline__ int ld_et(const int* __restrict__ p, long long i) {
    return g_et64 ? p[2 * i] : p[(int)i];
}

// ---------------- K-1: detect whether index buffers are int64 or int32 ----
// For int64 little-endian values in [0, 2^31), every odd 32-bit word is 0.
// For genuine int32 index data, that probability is ~0 across 64 entries.
__global__ void k_detect(const int* __restrict__ ei,
                         const int* __restrict__ et) {
    if (threadIdx.x == 0 && blockIdx.x == 0) {
        int a = 1, b = 1;
        for (int e = 0; e < 64; e++) {
            if (ei[2 * e + 1] != 0) a = 0;
            if (et[2 * e + 1] != 0) b = 0;
        }
        g_ei64 = a;
        g_et64 = b;
    }
}

// ---------------- K0: Wrel = comp @ basis, plus zeroing of count arrays ----
__global__ void k_init(const float* __restrict__ basis,
                       const float* __restrict__ comp) {
    int idx = blockIdx.x * blockDim.x + threadIdx.x;
    if (idx < NN) { g_deg_out[idx] = 0; g_cnt[idx] = 0; }
    if (idx < RR * DIN * H1) {
        int r  = idx / (DIN * H1);
        int io = idx % (DIN * H1);
        float s = 0.f;
#pragma unroll
        for (int b = 0; b < BB; b++)
            s += comp[r * BB + b] * basis[b * DIN * H1 + io];
        g_Wrel[idx] = s;
    }
}

// ---------------- CSR build ------------------------------------------------
__global__ void k_count(const int* __restrict__ ei) {
    int e = blockIdx.x * blockDim.x + threadIdx.x;
    if (e < EE) {
        int s = ld_ei(ei, e);
        int d = ld_ei(ei, (long long)EE + e);
        atomicAdd(&g_deg_out[s], 1);                 // src histogram
        atomicAdd(&g_cnt[d], 1);                     // dst histogram
    }
}

// ---- parallel exclusive scan of g_cnt -> g_off, 3 phases, full-chip ------
// Phase A: per-block (1024 elems) local exclusive scan + block total.
__global__ __launch_bounds__(1024) void k_scan_a() {
    __shared__ int sh[1024];
    int b = blockIdx.x, t = threadIdx.x;
    int i = b * 1024 + t;
    int v = (i < NN) ? g_cnt[i] : 0;
    sh[t] = v;
    __syncthreads();
    for (int d = 1; d < 1024; d <<= 1) {
        int u = (t >= d) ? sh[t - d] : 0;
        __syncthreads();
        sh[t] += u;
        __syncthreads();
    }
    if (i < NN) g_off[i] = sh[t] - v;                // local exclusive
    if (t == 1023) g_bsum[b] = sh[1023];             // block total
}

// Phase B: serial exclusive scan of the SCAN_NB block totals (L2-hot).
__global__ void k_scan_b() {
    if (threadIdx.x == 0 && blockIdx.x == 0) {
        int run = 0;
        for (int b = 0; b < SCAN_NB; b++) {
            int v = g_bsum[b];
            g_bsum[b] = run;
            run += v;
        }
        g_off[NN] = run;                             // == EE
    }
}

// Phase C: add block base; materialize cursor.
__global__ __launch_bounds__(1024) void k_scan_c() {
    int b = blockIdx.x, t = threadIdx.x;
    int i = b * 1024 + t;
    if (i < NN) {
        int o = g_off[i] + g_bsum[b];
        g_off[i]    = o;
        g_cursor[i] = o;
    }
}

__global__ void k_scatter(const int* __restrict__ ei,
                          const int* __restrict__ et) {
    int e = blockIdx.x * blockDim.x + threadIdx.x;
    if (e < EE) {
        int s = ld_ei(ei, e);
        int d = ld_ei(ei, (long long)EE + e);
        int r = ld_et(et, e);
        int pos = atomicAdd(&g_cursor[d], 1);
        g_csr[pos] = (unsigned)(s * RR + r);
    }
}

// ---------------- K1: xr[n,r,:] = x @ Wrel_r ; h_init = x @ loopW + b1 -----
// 64-node tile, 9 weight matrices. A stored transposed with +1 pad (scalar
// LDS, conflict-free); W read as float4 rows (LDS.128, conflict-free).
// Each thread: 4 nodes x 4 output cols -> 16 FFMA + 5 LDS per k.
__global__ __launch_bounds__(256) void k_xr(const float* __restrict__ x,
                                            const float* __restrict__ loopw,
                                            const float* __restrict__ bias1) {
    __shared__ __align__(16) float At[64][65];       // A transposed, padded
    __shared__ __align__(16) float Ws[64][64];       // current W
    int t  = threadIdx.x;
    int n0 = blockIdx.x * 64;

    for (int it = 0; it < 16; it++) {
        int idx = t + it * 256;
        int nl = idx >> 6, k = idx & 63;
        int n = n0 + nl;
        At[k][nl] = (n < NN) ? x[n * DIN + k] : 0.f;
    }

    int tx = t & 15, ty = t >> 4;                    // cols tx*4.., nodes ty*4..
    float b1r[4];
#pragma unroll
    for (int q = 0; q < 4; q++) b1r[q] = bias1[tx * 4 + q];

    for (int m = 0; m < 9; m++) {
        const float* W = (m < 8) ? (g_Wrel + m * DIN * H1) : loopw;
        __syncthreads();
        for (int it = 0; it < 16; it++) {
            int idx = t + it * 256;
            ((float*)Ws)[idx] = W[idx];
        }
        __syncthreads();

        float c[4][4];
#pragma unroll
        for (int j = 0; j < 4; j++)
#pragma unroll
            for (int q = 0; q < 4; q++) c[j][q] = 0.f;

#pragma unroll 8
        for (int k = 0; k < 64; k++) {
            float4 b = *(const float4*)&Ws[k][tx * 4];
            float a0 = At[k][ty * 4 + 0];
            float a1 = At[k][ty * 4 + 1];
            float a2 = At[k][ty * 4 + 2];
            float a3 = At[k][ty * 4 + 3];
            c[0][0] += a0 * b.x; c[0][1] += a0 * b.y; c[0][2] += a0 * b.z; c[0][3] += a0 * b.w;
            c[1][0] += a1 * b.x; c[1][1] += a1 * b.y; c[1][2] += a1 * b.z; c[1][3] += a1 * b.w;
            c[2][0] += a2 * b.x; c[2][1] += a2 * b.y; c[2][2] += a2 * b.z; c[2][3] += a2 * b.w;
            c[3][0] += a3 * b.x; c[3][1] += a3 * b.y; c[3][2] += a3 * b.z; c[3][3] += a3 * b.w;
        }

#pragma unroll
        for (int j = 0; j < 4; j++) {
            int n = n0 + ty * 4 + j;
            if (n < NN) {
                float4 o = make_float4(c[j][0], c[j][1], c[j][2], c[j][3]);
                if (m < 8) {
                    *(float4*)&g_xr[((size_t)n * 8 + m) * 64 + tx * 4] = o;
                } else {
                    o.x += b1r[0]; o.y += b1r[1]; o.z += b1r[2]; o.w += b1r[3];
                    *(float4*)&g_h[n * 64 + tx * 4] = o;
                }
            }
        }
    }
}

// ---------------- K2: h[d] += sum over in-edges of xr[src*8+et] -----------
// warp per dst; csr indices fetched coalesced then shfl'd; each lane owns
// dims {2l, 2l+1} -> the warp reads the full 256B row contiguously.
__global__ __launch_bounds__(256) void k_agg1() {
    int w = (blockIdx.x * 256 + threadIdx.x) >> 5;   // dst node
    int l = threadIdx.x & 31;
    int beg = g_off[w], end = g_off[w + 1];
    float ax = 0.f, ay = 0.f;
    for (int cb = beg; cb < end; cb += 32) {
        int mcnt = min(32, end - cb);
        unsigned myrow = (l < mcnt) ? g_csr[cb + l] : 0u;
#pragma unroll 4
        for (int j = 0; j < mcnt; j++) {
            unsigned row = __shfl_sync(0xffffffffu, myrow, j);
            float2 v = *(const float2*)&g_xr[(size_t)row * 64 + 2 * l];
            ax += v.x; ay += v.y;
        }
    }
    float2 h = *(float2*)&g_h[w * 64 + 2 * l];
    h.x += ax; h.y += ay;
    *(float2*)&g_h[w * 64 + 2 * l] = h;
}

// ---------------- K3: GraphConv gather + fused 64x64 GEMM + bias ----------
__global__ __launch_bounds__(256) void k_out(const float* __restrict__ w2,
                                             const float* __restrict__ bias2,
                                             float* __restrict__ out) {
    __shared__ __align__(16) float Ws[64][64];       // 16 KB
    __shared__ float vbuf[8][64];                    // 2 KB
    int t = threadIdx.x;
    for (int it = 0; it < 16; it++)
        ((float*)Ws)[t + it * 256] = w2[t + it * 256];
    __syncthreads();

    int w  = (blockIdx.x * 256 + t) >> 5;            // dst node
    int wl = t >> 5;
    int l  = t & 31;
    int beg = g_off[w], end = g_off[w + 1];

    float ax = 0.f, ay = 0.f;
    for (int cb = beg; cb < end; cb += 32) {
        int mcnt = min(32, end - cb);
        unsigned myrow = (l < mcnt) ? g_csr[cb + l] : 0u;
#pragma unroll 4
        for (int j = 0; j < mcnt; j++) {
            unsigned row = __shfl_sync(0xffffffffu, myrow, j);
            int src = (int)(row >> 3);
            float sc = rsqrtf((float)max(g_deg_out[src], 1));
            float2 v = *(const float2*)&g_h[src * 64 + 2 * l];
            ax += v.x * sc; ay += v.y * sc;
        }
    }
    float si = rsqrtf((float)max(end - beg, 1));
    ax *= si; ay *= si;

    vbuf[wl][2 * l]     = ax;
    vbuf[wl][2 * l + 1] = ay;
    __syncwarp();

    float ox = 0.f, oy = 0.f;
#pragma unroll 16
    for (int i = 0; i < 64; i++) {
        float v = vbuf[wl][i];                       // broadcast
        float2 wv = *(const float2*)&Ws[i][2 * l];   // conflict-free
        ox += v * wv.x; oy += v * wv.y;
    }
    ox += bias2[2 * l];
    oy += bias2[2 * l + 1];
    out[w * 64 + 2 * l]     = ox;
    out[w * 64 + 2 * l + 1] = oy;
}

// ---------------- launch ---------------------------------------------------
extern "C" void kernel_launch(void* const* d_in, const int* in_sizes, int n_in,
                              void* d_out, int out_size) {
    const float* x     = (const float*)d_in[0];
    const int*   ei    = (const int*)d_in[1];     // edge_index (int32 or int64)
    // d_in[2] = edge_norm (unused by the reference computation)
    const int*   et    = (const int*)d_in[3];     // edge_type  (int32 or int64)
    const float* basis = (const float*)d_in[4];
    const float* comp  = (const float*)d_in[5];
    const float* loopw = (const float*)d_in[6];
    const float* b1    = (const float*)d_in[7];
    const float* w2    = (const float*)d_in[8];
    const float* b2    = (const float*)d_in[9];
    float* out = (float*)d_out;

    k_detect <<<1, 32>>>(ei, et);
    k_init   <<<(NN + 255) / 256, 256>>>(basis, comp);
    k_count  <<<(EE + 255) / 256, 256>>>(ei);
    k_scan_a <<<SCAN_NB, 1024>>>();
    k_scan_b <<<1, 32>>>();
    k_scan_c <<<SCAN_NB, 1024>>>();
    k_scatter<<<(EE + 255) / 256, 256>>>(ei, et);
    k_xr     <<<(NN + 63) / 64, 256>>>(x, loopw, b1);
    k_agg1   <<<NN / 8, 256>>>();
    k_out    <<<NN / 8, 256>>>(w2, b2, out);
}

// round 14
// speedup vs baseline: 1.3028x; 1.0082x over previous
#include <cuda_runtime.h>
#include <cstdint>

#define NN 50000
#define EE 1000000
#define RR 8
#define BB 30
#define DIN 64
#define H1 64
#define H2 64
#define SCAN_NB ((NN + 1023) / 1024)   // 49

// ---------------- scratch (static device globals; no runtime allocation) ---
__device__ __align__(16) float g_Wrel[RR * DIN * H1];       // 128 KB
__device__ __align__(16) float g_xr[(size_t)NN * RR * H1];  // 102.4 MB xr[n][r][o]
__device__ __align__(16) float g_h[NN * H1];                // 12.8 MB
__device__ int      g_deg_out[NN];
__device__ int      g_cnt[NN];
__device__ int      g_off[NN + 1];
__device__ int      g_cursor[NN];
__device__ int      g_bsum[SCAN_NB];
__device__ unsigned g_csr[EE];                              // src*8 + etype, CSR by dst
__device__ int      g_ei64;                                 // edge_index is int64?
__device__ int      g_et64;                                 // edge_type  is int64?

// Read index element i from a buffer that is either int32[] or int64[] (LE).
__device__ __forceinline__ int ld_ei(const int* __restrict__ p, long long i) {
    return g_ei64 ? p[2 * i] : p[(int)i];
}
__device__ __forceinline__ int ld_et(const int* __restrict__ p, long long i) {
    return g_et64 ? p[2 * i] : p[(int)i];
}

// ---------------- packed f32x2 helpers (FFMA2: 2 FMA/instr, full fp32 rate) -
__device__ __forceinline__ void ffma2(unsigned long long& c,
                                      unsigned long long a,
                                      unsigned long long b) {
    asm("fma.rn.f32x2 %0, %1, %2, %0;" : "+l"(c) : "l"(a), "l"(b));
}
__device__ __forceinline__ unsigned long long fdup(float x) {
    unsigned long long r;
    asm("mov.b64 %0, {%1, %1};" : "=l"(r) : "f"(x));
    return r;
}
__device__ __forceinline__ float2 unpk(unsigned long long v) {
    float2 r;
    asm("mov.b64 {%0, %1}, %2;" : "=f"(r.x), "=f"(r.y) : "l"(v));
    return r;
}

// ---------------- K-1: detect whether index buffers are int64 or int32 ----
__global__ void k_detect(const int* __restrict__ ei,
                         const int* __restrict__ et) {
    if (threadIdx.x == 0 && blockIdx.x == 0) {
        int a = 1, b = 1;
        for (int e = 0; e < 64; e++) {
            if (ei[2 * e + 1] != 0) a = 0;
            if (et[2 * e + 1] != 0) b = 0;
        }
        g_ei64 = a;
        g_et64 = b;
    }
}

// ---------------- K0: Wrel = comp @ basis, plus zeroing of count arrays ----
__global__ void k_init(const float* __restrict__ basis,
                       const float* __restrict__ comp) {
    int idx = blockIdx.x * blockDim.x + threadIdx.x;
    if (idx < NN) { g_deg_out[idx] = 0; g_cnt[idx] = 0; }
    if (idx < RR * DIN * H1) {
        int r  = idx / (DIN * H1);
        int io = idx % (DIN * H1);
        float s = 0.f;
#pragma unroll
        for (int b = 0; b < BB; b++)
            s += comp[r * BB + b] * basis[b * DIN * H1 + io];
        g_Wrel[idx] = s;
    }
}

// ---------------- CSR build ------------------------------------------------
__global__ void k_count(const int* __restrict__ ei) {
    int e = blockIdx.x * blockDim.x + threadIdx.x;
    if (e < EE) {
        int s = ld_ei(ei, e);
        int d = ld_ei(ei, (long long)EE + e);
        atomicAdd(&g_deg_out[s], 1);                 // src histogram
        atomicAdd(&g_cnt[d], 1);                     // dst histogram
    }
}

// ---- parallel exclusive scan of g_cnt -> g_off, 3 phases, full-chip ------
__global__ __launch_bounds__(1024) void k_scan_a() {
    __shared__ int sh[1024];
    int b = blockIdx.x, t = threadIdx.x;
    int i = b * 1024 + t;
    int v = (i < NN) ? g_cnt[i] : 0;
    sh[t] = v;
    __syncthreads();
    for (int d = 1; d < 1024; d <<= 1) {
        int u = (t >= d) ? sh[t - d] : 0;
        __syncthreads();
        sh[t] += u;
        __syncthreads();
    }
    if (i < NN) g_off[i] = sh[t] - v;                // local exclusive
    if (t == 1023) g_bsum[b] = sh[1023];             // block total
}

// Phase B: parallel 64-thread scan of the SCAN_NB block totals.
__global__ void k_scan_b() {
    __shared__ int sh[64];
    int t = threadIdx.x;
    int v = (t < SCAN_NB) ? g_bsum[t] : 0;
    sh[t] = v;
    __syncthreads();
    for (int d = 1; d < 64; d <<= 1) {
        int u = (t >= d) ? sh[t - d] : 0;
        __syncthreads();
        sh[t] += u;
        __syncthreads();
    }
    if (t < SCAN_NB) g_bsum[t] = sh[t] - v;          // exclusive base per block
    if (t == 63) g_off[NN] = sh[63];                 // == EE
}

// Phase C: add block base; materialize cursor.
__global__ __launch_bounds__(1024) void k_scan_c() {
    int b = blockIdx.x, t = threadIdx.x;
    int i = b * 1024 + t;
    if (i < NN) {
        int o = g_off[i] + g_bsum[b];
        g_off[i]    = o;
        g_cursor[i] = o;
    }
}

__global__ void k_scatter(const int* __restrict__ ei,
                          const int* __restrict__ et) {
    int e = blockIdx.x * blockDim.x + threadIdx.x;
    if (e < EE) {
        int s = ld_ei(ei, e);
        int d = ld_ei(ei, (long long)EE + e);
        int r = ld_et(et, e);
        int pos = atomicAdd(&g_cursor[d], 1);
        g_csr[pos] = (unsigned)(s * RR + r);
    }
}

// ---------------- K1: xr[n,r,:] = x @ Wrel_r ; h_init = x @ loopW + b1 -----
// FFMA2 version. 128 threads cover 128 nodes x 64 cols; thread tile 8x8.
// A staged in smem as At[k][node] (conflict-free stores + broadcast loads);
// B read from global as u64 pairs via __ldg (W tile L1-resident, no staging,
// no per-matrix barriers). Per k per thread: 4 LDS.64 + 4 LDG.64 + 8 packs
// + 32 FFMA2 -> fma-pipe bound at full 128 MAC/cyc/SM.
__global__ __launch_bounds__(128) void k_xr(const float* __restrict__ x,
                                            const float* __restrict__ loopw,
                                            const float* __restrict__ bias1) {
    __shared__ float At[64][128];                    // 32 KB
    int t  = threadIdx.x;
    int n0 = blockIdx.x * 128;
    int gn = n0 + t;

    if (gn < NN) {
#pragma unroll
        for (int k4 = 0; k4 < 16; k4++) {
            float4 v = *(const float4*)&x[(size_t)gn * 64 + k4 * 4];
            At[k4 * 4 + 0][t] = v.x;
            At[k4 * 4 + 1][t] = v.y;
            At[k4 * 4 + 2][t] = v.z;
            At[k4 * 4 + 3][t] = v.w;
        }
    } else {
#pragma unroll
        for (int k4 = 0; k4 < 16; k4++) {
            At[k4 * 4 + 0][t] = 0.f;
            At[k4 * 4 + 1][t] = 0.f;
            At[k4 * 4 + 2][t] = 0.f;
            At[k4 * 4 + 3][t] = 0.f;
        }
    }
    __syncthreads();

    int tx = t & 7, ty = t >> 3;                     // cols tx*8.., nodes ty*8..
    float4 b1a = *(const float4*)&bias1[tx * 8];
    float4 b1b = *(const float4*)&bias1[tx * 8 + 4];

    for (int m = 0; m < 9; m++) {
        const float* W = (m < 8) ? (g_Wrel + m * DIN * H1) : loopw;
        const unsigned long long* Wp = (const unsigned long long*)W;

        unsigned long long c[8][4];
#pragma unroll
        for (int j = 0; j < 8; j++)
#pragma unroll
            for (int p = 0; p < 4; p++) c[j][p] = 0ull;

#pragma unroll 8
        for (int k = 0; k < 64; k++) {
            unsigned long long b0 = __ldg(&Wp[k * 32 + tx * 4 + 0]);
            unsigned long long b1 = __ldg(&Wp[k * 32 + tx * 4 + 1]);
            unsigned long long b2 = __ldg(&Wp[k * 32 + tx * 4 + 2]);
            unsigned long long b3 = __ldg(&Wp[k * 32 + tx * 4 + 3]);
#pragma unroll
            for (int q = 0; q < 4; q++) {
                float2 ap = *(const float2*)&At[k][ty * 8 + 2 * q];
                unsigned long long a0 = fdup(ap.x);
                unsigned long long a1 = fdup(ap.y);
                ffma2(c[2 * q][0], a0, b0);
                ffma2(c[2 * q][1], a0, b1);
                ffma2(c[2 * q][2], a0, b2);
                ffma2(c[2 * q][3], a0, b3);
                ffma2(c[2 * q + 1][0], a1, b0);
                ffma2(c[2 * q + 1][1], a1, b1);
                ffma2(c[2 * q + 1][2], a1, b2);
                ffma2(c[2 * q + 1][3], a1, b3);
            }
        }

#pragma unroll
        for (int j = 0; j < 8; j++) {
            int n = n0 + ty * 8 + j;
            if (n < NN) {
                float2 p0 = unpk(c[j][0]);
                float2 p1 = unpk(c[j][1]);
                float2 p2 = unpk(c[j][2]);
                float2 p3 = unpk(c[j][3]);
                float4 oA = make_float4(p0.x, p0.y, p1.x, p1.y);
                float4 oB = make_float4(p2.x, p2.y, p3.x, p3.y);
                if (m < 8) {
                    float* dst = &g_xr[((size_t)n * 8 + m) * 64 + tx * 8];
                    *(float4*)dst       = oA;
                    *(float4*)(dst + 4) = oB;
                } else {
                    oA.x += b1a.x; oA.y += b1a.y; oA.z += b1a.z; oA.w += b1a.w;
                    oB.x += b1b.x; oB.y += b1b.y; oB.z += b1b.z; oB.w += b1b.w;
                    float* dst = &g_h[n * 64 + tx * 8];
                    *(float4*)dst       = oA;
                    *(float4*)(dst + 4) = oB;
                }
            }
        }
    }
}

// ---------------- K2: h[d] += sum over in-edges of xr[src*8+et] -----------
__global__ __launch_bounds__(256) void k_agg1() {
    int w = (blockIdx.x * 256 + threadIdx.x) >> 5;   // dst node
    int l = threadIdx.x & 31;
    int beg = g_off[w], end = g_off[w + 1];
    float ax = 0.f, ay = 0.f;
    for (int cb = beg; cb < end; cb += 32) {
        int mcnt = min(32, end - cb);
        unsigned myrow = (l < mcnt) ? g_csr[cb + l] : 0u;
#pragma unroll 4
        for (int j = 0; j < mcnt; j++) {
            unsigned row = __shfl_sync(0xffffffffu, myrow, j);
            float2 v = *(const float2*)&g_xr[(size_t)row * 64 + 2 * l];
            ax += v.x; ay += v.y;
        }
    }
    float2 h = *(float2*)&g_h[w * 64 + 2 * l];
    h.x += ax; h.y += ay;
    *(float2*)&g_h[w * 64 + 2 * l] = h;
}

// ---------------- K3: GraphConv gather + fused 64x64 GEMM + bias ----------
__global__ __launch_bounds__(256) void k_out(const float* __restrict__ w2,
                                             const float* __restrict__ bias2,
                                             float* __restrict__ out) {
    __shared__ __align__(16) float Ws[64][64];       // 16 KB
    __shared__ float vbuf[8][64];                    // 2 KB
    int t = threadIdx.x;
    for (int it = 0; it < 16; it++)
        ((float*)Ws)[t + it * 256] = w2[t + it * 256];
    __syncthreads();

    int w  = (blockIdx.x * 256 + t) >> 5;            // dst node
    int wl = t >> 5;
    int l  = t & 31;
    int beg = g_off[w], end = g_off[w + 1];

    float ax = 0.f, ay = 0.f;
    for (int cb = beg; cb < end; cb += 32) {
        int mcnt = min(32, end - cb);
        unsigned myrow = (l < mcnt) ? g_csr[cb + l] : 0u;
#pragma unroll 4
        for (int j = 0; j < mcnt; j++) {
            unsigned row = __shfl_sync(0xffffffffu, myrow, j);
            int src = (int)(row >> 3);
            float sc = rsqrtf((float)max(g_deg_out[src], 1));
            float2 v = *(const float2*)&g_h[src * 64 + 2 * l];
            ax += v.x * sc; ay += v.y * sc;
        }
    }
    float si = rsqrtf((float)max(end - beg, 1));
    ax *= si; ay *= si;

    vbuf[wl][2 * l]     = ax;
    vbuf[wl][2 * l + 1] = ay;
    __syncwarp();

    float ox = 0.f, oy = 0.f;
#pragma unroll 16
    for (int i = 0; i < 64; i++) {
        float v = vbuf[wl][i];                       // broadcast
        float2 wv = *(const float2*)&Ws[i][2 * l];   // conflict-free
        ox += v * wv.x; oy += v * wv.y;
    }
    ox += bias2[2 * l];
    oy += bias2[2 * l + 1];
    out[w * 64 + 2 * l]     = ox;
    out[w * 64 + 2 * l + 1] = oy;
}

// ---------------- launch ---------------------------------------------------
extern "C" void kernel_launch(void* const* d_in, const int* in_sizes, int n_in,
                              void* d_out, int out_size) {
    const float* x     = (const float*)d_in[0];
    const int*   ei    = (const int*)d_in[1];     // edge_index (int32 or int64)
    // d_in[2] = edge_norm (unused by the reference computation)
    const int*   et    = (const int*)d_in[3];     // edge_type  (int32 or int64)
    const float* basis = (const float*)d_in[4];
    const float* comp  = (const float*)d_in[5];
    const float* loopw = (const float*)d_in[6];
    const float* b1    = (const float*)d_in[7];
    const float* w2    = (const float*)d_in[8];
    const float* b2    = (const float*)d_in[9];
    float* out = (float*)d_out;

    k_detect <<<1, 32>>>(ei, et);
    k_init   <<<(NN + 255) / 256, 256>>>(basis, comp);
    k_count  <<<(EE + 255) / 256, 256>>>(ei);
    k_scan_a <<<SCAN_NB, 1024>>>();
    k_scan_b <<<1, 64>>>();
    k_scan_c <<<SCAN_NB, 1024>>>();
    k_scatter<<<(EE + 255) / 256, 256>>>(ei, et);
    k_xr     <<<(NN + 127) / 128, 128>>>(x, loopw, b1);
    k_agg1   <<<NN / 8, 256>>>();
    k_out    <<<NN / 8, 256>>>(w2, b2, out);
}